// round 3
// baseline (speedup 1.0000x reference)
#include <cuda_runtime.h>
#include <cfloat>
#include <cstdint>

#define NN 50000
#define EE 800000
#define DD 128
#define BB 8

// ---------------- scratch (device globals; no allocation allowed) ----------------
__device__ float g_x [NN*DD];
__device__ float g_A1[NN*DD];
__device__ float g_B1[NN*DD];
__device__ float g_A2[NN*DD];
__device__ float g_B2[NN*DD];
__device__ float g_S1[NN*DD];
__device__ float g_S2[NN*DD];
__device__ float g_fi[NN*DD];
__device__ float g_fo[NN*DD];
__device__ float g_t [NN*2*DD];

__device__ int   g_indeg[NN], g_outdeg[NN];
__device__ int   g_cur1[NN],  g_cur2[NN];
__device__ int   g_dst_off[NN+1], g_src_off[NN+1];
__device__ int   g_csr_dst[EE];   // for dst-grouped edges: the src endpoint
__device__ int   g_csr_src[EE];   // for src-grouped edges: the dst endpoint
__device__ float g_inv_dst[NN], g_inv_src[NN];
__device__ int   g_cnt[BB];

// ---------------- small utility kernels ----------------
__global__ void k_zero(float* out)
{
    int i = blockIdx.x * blockDim.x + threadIdx.x;
    int stride = gridDim.x * blockDim.x;
    for (int k = i; k < NN; k += stride) {
        g_indeg[k] = 0; g_outdeg[k] = 0; g_cur1[k] = 0; g_cur2[k] = 0;
    }
    if (i < BB) g_cnt[i] = 0;
    if (i < BB * 4 * DD) out[i] = ((i & 511) < 256) ? -FLT_MAX : 0.f;
}

__global__ void k_degree(const int* __restrict__ src, const int* __restrict__ dst)
{
    int e = blockIdx.x * blockDim.x + threadIdx.x;
    if (e < EE) {
        atomicAdd(&g_indeg[dst[e]], 1);
        atomicAdd(&g_outdeg[src[e]], 1);
    }
}

// single-block-per-array exclusive scan (N = 50000, 1024 threads, chunked)
__global__ void k_scan()
{
    const int* deg = (blockIdx.x == 0) ? g_indeg : g_outdeg;
    int* off       = (blockIdx.x == 0) ? g_dst_off : g_src_off;
    __shared__ int ssum[1024];
    int t = threadIdx.x;
    const int chunk = (NN + 1023) / 1024;          // 49
    int s0 = t * chunk;
    int s1 = (s0 + chunk < NN) ? s0 + chunk : NN;
    int s = 0;
    for (int i = s0; i < s1; i++) s += deg[i];
    ssum[t] = s;
    __syncthreads();
    for (int d = 1; d < 1024; d <<= 1) {
        int v = 0;
        if (t >= d) v = ssum[t - d];
        __syncthreads();
        if (t >= d) ssum[t] += v;
        __syncthreads();
    }
    int base = t ? ssum[t - 1] : 0;
    for (int i = s0; i < s1; i++) { off[i] = base; base += deg[i]; }
    if (t == 0) off[NN] = ssum[1023];
}

__global__ void k_fill(const int* __restrict__ src, const int* __restrict__ dst)
{
    int e = blockIdx.x * blockDim.x + threadIdx.x;
    if (e < EE) {
        int s = src[e], d = dst[e];
        int p = g_dst_off[d] + atomicAdd(&g_cur1[d], 1);
        g_csr_dst[p] = s;
        int q = g_src_off[s] + atomicAdd(&g_cur2[s], 1);
        g_csr_src[q] = d;
    }
}

__global__ void k_invdeg(const int* __restrict__ batch)
{
    int i = blockIdx.x * blockDim.x + threadIdx.x;
    if (i < NN) {
        int di = g_indeg[i];  g_inv_dst[i] = di ? 1.f / (float)di : 0.f;
        int dо = g_outdeg[i]; g_inv_src[i] = dо ? 1.f / (float)dо : 0.f;
        atomicAdd(&g_cnt[batch[i]], 1);
    }
}

// ---------------- edge aggregation: S[i] = inv[i] * sum_j relu(A[i] + B[j]) ----------------
// one warp per node, 4 floats per lane; A/B tables are L2-resident (25.6 MB each)
__global__ void k_edge_agg(const float* __restrict__ Ab, const float* __restrict__ Bb,
                           const int* __restrict__ off, const int* __restrict__ csr,
                           const float* __restrict__ inv, float* __restrict__ S)
{
    int gw   = (blockIdx.x * blockDim.x + threadIdx.x) >> 5;
    int lane = threadIdx.x & 31;
    if (gw >= NN) return;
    float4 a = *(const float4*)(Ab + (size_t)gw * DD + lane * 4);
    float4 acc = make_float4(0.f, 0.f, 0.f, 0.f);
    int e0 = off[gw], e1 = off[gw + 1];
    for (int e = e0; e < e1; e++) {
        int j = csr[e];
        float4 b = *(const float4*)(Bb + (size_t)j * DD + lane * 4);
        acc.x += fmaxf(a.x + b.x, 0.f);
        acc.y += fmaxf(a.y + b.y, 0.f);
        acc.z += fmaxf(a.z + b.z, 0.f);
        acc.w += fmaxf(a.w + b.w, 0.f);
    }
    float s = inv[gw];
    float4 r = make_float4(acc.x * s, acc.y * s, acc.z * s, acc.w * s);
    *(float4*)(S + (size_t)gw * DD + lane * 4) = r;
}

// ---------------- tiled fp32 GEMM: C[M x NCOL] = cat(A segs)[M x K] @ W[K x NCOL] (+epilogue) ----------------
#define EPI_BIAS     0
#define EPI_MASKBIAS 1
#define EPI_RELU     2
#define EPI_RES      3

template<int NSEG, int EPI>
__global__ __launch_bounds__(256, 2) void gemm_k(
    const float* __restrict__ P0, int l0,
    const float* __restrict__ P1, int l1,
    const float* __restrict__ P2, int l2,
    const float* __restrict__ W,
    const float* __restrict__ bias,
    const int*   __restrict__ mask,
    const float* __restrict__ Cprev,
    float* __restrict__ C, int M, int NCOL)
{
    __shared__ __align__(16) float As[16][132];
    __shared__ __align__(16) float Ws[16][128];
    const int tid = threadIdx.x;
    const int m0  = blockIdx.x * 128;
    const int n0  = blockIdx.y * 128;
    const int K   = NSEG * 128;
    const int ty = tid >> 4, tx = tid & 15;

    float acc[8][8];
#pragma unroll
    for (int i = 0; i < 8; i++)
#pragma unroll
        for (int j = 0; j < 8; j++) acc[i][j] = 0.f;

    for (int kt = 0; kt < K; kt += 16) {
        const float* Ap = P0; int lda = l0;
        if (NSEG >= 2) {
            int seg = kt >> 7;
            if (seg == 1)              { Ap = P1; lda = l1; }
            if (NSEG >= 3 && seg == 2) { Ap = P2; lda = l2; }
        }
        int kcol = kt & 127;
        // A tile: 128 rows x 16 k, transposed into As[k][m]
#pragma unroll
        for (int it = 0; it < 2; it++) {
            int lid = tid + it * 256;
            int row = lid >> 2, kq = (lid & 3) * 4;
            int grow = m0 + row;
            float4 v = make_float4(0.f, 0.f, 0.f, 0.f);
            if (grow < M) v = *(const float4*)(Ap + (size_t)grow * lda + kcol + kq);
            As[kq + 0][row] = v.x;
            As[kq + 1][row] = v.y;
            As[kq + 2][row] = v.z;
            As[kq + 3][row] = v.w;
        }
        // W tile: 16 k x 128 n
#pragma unroll
        for (int it = 0; it < 2; it++) {
            int lid = tid + it * 256;
            int row = lid >> 5, c4 = (lid & 31) * 4;
            *(float4*)&Ws[row][c4] = *(const float4*)(W + (size_t)(kt + row) * NCOL + n0 + c4);
        }
        __syncthreads();
#pragma unroll
        for (int kk = 0; kk < 16; kk++) {
            float4 a0 = *(const float4*)&As[kk][ty * 8];
            float4 a1 = *(const float4*)&As[kk][ty * 8 + 4];
            float4 b0 = *(const float4*)&Ws[kk][tx * 8];
            float4 b1 = *(const float4*)&Ws[kk][tx * 8 + 4];
            float a[8] = {a0.x, a0.y, a0.z, a0.w, a1.x, a1.y, a1.z, a1.w};
            float b[8] = {b0.x, b0.y, b0.z, b0.w, b1.x, b1.y, b1.z, b1.w};
#pragma unroll
            for (int i = 0; i < 8; i++)
#pragma unroll
                for (int j = 0; j < 8; j++)
                    acc[i][j] += a[i] * b[j];
        }
        __syncthreads();
    }

#pragma unroll
    for (int i = 0; i < 8; i++) {
        int grow = m0 + ty * 8 + i;
        if (grow < M) {
#pragma unroll
            for (int j = 0; j < 8; j++) {
                int gcol = n0 + tx * 8 + j;
                float v = acc[i][j];
                if (EPI == EPI_BIAS)          { if (bias) v += bias[gcol]; }
                else if (EPI == EPI_MASKBIAS) { if (mask[grow] > 0) v += bias[gcol]; }
                else if (EPI == EPI_RELU)     { v = fmaxf(v + bias[gcol], 0.f); }
                else /* EPI_RES */            { v += bias[gcol] + Cprev[(size_t)grow * NCOL + gcol]; }
                C[(size_t)grow * NCOL + gcol] = v;
            }
        }
    }
}

// ---------------- pooling ----------------
__device__ __forceinline__ void atomicMaxF(float* addr, float val)
{
    int old = __float_as_int(*addr);
    while (__int_as_float(old) < val) {
        int prev = atomicCAS((int*)addr, old, __float_as_int(val));
        if (prev == old) break;
        old = prev;
    }
}

__global__ void k_pool(const float* __restrict__ y, const int* __restrict__ batch,
                       float* __restrict__ out)
{
    int t = threadIdx.x;                          // column 0..255
    int chunk = (NN + gridDim.x - 1) / gridDim.x;
    int r0 = blockIdx.x * chunk;
    int r1 = (r0 + chunk < NN) ? r0 + chunk : NN;
    if (r0 >= r1) return;
    int g = batch[r0];
    float mx = -FLT_MAX, sm = 0.f;
    for (int r = r0; r < r1; r++) {
        int gb = batch[r];
        float v = y[(size_t)r * 256 + t];
        if (gb != g) {
            atomicMaxF(&out[g * 512 + t], mx);
            atomicAdd(&out[g * 512 + 256 + t], sm);
            g = gb; mx = -FLT_MAX; sm = 0.f;
        }
        mx = fmaxf(mx, v);
        sm += v;
    }
    atomicMaxF(&out[g * 512 + t], mx);
    atomicAdd(&out[g * 512 + 256 + t], sm);
}

__global__ void k_finalize(float* out)
{
    int b = blockIdx.x, c = threadIdx.x;
    int cnt = g_cnt[b];
    if (cnt > 0) out[b * 512 + 256 + c] *= 1.f / (float)cnt;
}

// ---------------- launch ----------------
extern "C" void kernel_launch(void* const* d_in, const int* in_sizes, int n_in,
                              void* d_out, int out_size)
{
    const float* nodes = (const float*)d_in[0];
    const int*   edges = (const int*)  d_in[1];
    const int*   batch = (const int*)  d_in[2];
    const float* W_enc = (const float*)d_in[3];
    const float* b_enc = (const float*)d_in[4];
    const float* Wp1   = (const float*)d_in[5];
    const float* bp1   = (const float*)d_in[6];
    const float* Wp2   = (const float*)d_in[7];
    const float* bp2   = (const float*)d_in[8];
    const float* Wc1   = (const float*)d_in[9];
    const float* bc1   = (const float*)d_in[10];
    const float* Wc2   = (const float*)d_in[11];
    const float* bc2   = (const float*)d_in[12];
    const float* Wf1   = (const float*)d_in[13];
    const float* bf1   = (const float*)d_in[14];
    const float* Wf2   = (const float*)d_in[15];
    const float* bf2   = (const float*)d_in[16];
    const float* Wconv = (const float*)d_in[17];
    const float* bconv = (const float*)d_in[18];
    float* out = (float*)d_out;

    const int* src = edges;        // edges[0]
    const int* dst = edges + EE;   // edges[1]

    float *x, *A1, *B1, *A2, *B2, *S1, *S2, *fi, *fo, *tb, *invd, *invs;
    int *indeg, *outdeg, *doff, *soff, *csrd, *csrs;
    cudaGetSymbolAddress((void**)&x,  g_x);
    cudaGetSymbolAddress((void**)&A1, g_A1);
    cudaGetSymbolAddress((void**)&B1, g_B1);
    cudaGetSymbolAddress((void**)&A2, g_A2);
    cudaGetSymbolAddress((void**)&B2, g_B2);
    cudaGetSymbolAddress((void**)&S1, g_S1);
    cudaGetSymbolAddress((void**)&S2, g_S2);
    cudaGetSymbolAddress((void**)&fi, g_fi);
    cudaGetSymbolAddress((void**)&fo, g_fo);
    cudaGetSymbolAddress((void**)&tb, g_t);
    cudaGetSymbolAddress((void**)&invd, g_inv_dst);
    cudaGetSymbolAddress((void**)&invs, g_inv_src);
    cudaGetSymbolAddress((void**)&indeg,  g_indeg);
    cudaGetSymbolAddress((void**)&outdeg, g_outdeg);
    cudaGetSymbolAddress((void**)&doff, g_dst_off);
    cudaGetSymbolAddress((void**)&soff, g_src_off);
    cudaGetSymbolAddress((void**)&csrd, g_csr_dst);
    cudaGetSymbolAddress((void**)&csrs, g_csr_src);

    const int gx = (NN + 127) / 128;   // 391
    dim3 blk(256);
    dim3 g128(gx, 1), g256(gx, 2);
    int egrid = (EE + 255) / 256;

    // CSR + degrees + output init
    k_zero<<<256, 256>>>(out);
    k_degree<<<egrid, 256>>>(src, dst);
    k_scan<<<2, 1024>>>();
    k_fill<<<egrid, 256>>>(src, dst);
    k_invdeg<<<(NN + 255) / 256, 256>>>(batch);

    // encoder: x = nodes @ W_enc + b_enc     (K=256 as two 128 segments)
    gemm_k<2, EPI_BIAS><<<g128, blk>>>(nodes, 256, nodes + 128, 256, nullptr, 0,
                                       W_enc, b_enc, nullptr, nullptr, x, NN, 128);

    for (int it = 0; it < 2; it++) {
        // per-node halves of the edge MLP first layer (bias folded into A)
        gemm_k<1, EPI_BIAS><<<g128, blk>>>(x, 128, nullptr, 0, nullptr, 0,
                                           Wp1,             bp1,     nullptr, nullptr, A1, NN, 128);
        gemm_k<1, EPI_BIAS><<<g128, blk>>>(x, 128, nullptr, 0, nullptr, 0,
                                           Wp1 + 128 * 128, nullptr, nullptr, nullptr, B1, NN, 128);
        gemm_k<1, EPI_BIAS><<<g128, blk>>>(x, 128, nullptr, 0, nullptr, 0,
                                           Wc1,             bc1,     nullptr, nullptr, A2, NN, 128);
        gemm_k<1, EPI_BIAS><<<g128, blk>>>(x, 128, nullptr, 0, nullptr, 0,
                                           Wc1 + 128 * 128, nullptr, nullptr, nullptr, B2, NN, 128);
        // edge sweeps (linearity of W2 => sum relu first, GEMM after)
        k_edge_agg<<<6250, 256>>>(A1, B1, doff, csrd, invd, S1);   // parent: group by dst
        k_edge_agg<<<6250, 256>>>(A2, B2, soff, csrs, invs, S2);   // child:  group by src
        // second layer of edge MLP applied to normalized sums
        gemm_k<1, EPI_MASKBIAS><<<g128, blk>>>(S1, 128, nullptr, 0, nullptr, 0,
                                               Wp2, bp2, indeg,  nullptr, fi, NN, 128);
        gemm_k<1, EPI_MASKBIAS><<<g128, blk>>>(S2, 128, nullptr, 0, nullptr, 0,
                                               Wc2, bc2, outdeg, nullptr, fo, NN, 128);
        // t = relu([x|fi|fo] @ Wf1 + bf1)   (K=384, NCOL=256)
        gemm_k<3, EPI_RELU><<<g256, blk>>>(x, 128, fi, 128, fo, 128,
                                           Wf1, bf1, nullptr, nullptr, tb, NN, 256);
        // x = x + t @ Wf2 + bf2             (K=256, residual epilogue, in-place on x)
        gemm_k<2, EPI_RES><<<g128, blk>>>(tb, 256, tb + 128, 256, nullptr, 0,
                                          Wf2, bf2, nullptr, x, x, NN, 128);
    }

    // conv1d(k=1): y = x @ Wconv + bconv  -> reuse tb as y [N,256]
    gemm_k<1, EPI_BIAS><<<g256, blk>>>(x, 128, nullptr, 0, nullptr, 0,
                                       Wconv, bconv, nullptr, nullptr, tb, NN, 256);

    // global max / mean pool per graph
    k_pool<<<128, 256>>>(tb, batch, out);
    k_finalize<<<BB, 256>>>(out);
}

// round 10
// speedup vs baseline: 1.3973x; 1.3973x over previous
#include <cuda_runtime.h>
#include <cuda_bf16.h>
#include <mma.h>
#include <cfloat>
#include <cstdint>
using namespace nvcuda;

#define NN 50000
#define EE 800000
#define BB 8

// ======================= device global scratch =======================
__device__ float g_x[NN * 128];          // node embedding fp32
__device__ float g_P[NN * 512];          // [A1|B1|A2|B2] fp32; reused as y[N,256]
__device__ __align__(256) __nv_bfloat16 g_nbf[NN * 512];   // nodes hi/lo (per-128 seg pairs)
__device__ __align__(256) __nv_bfloat16 g_cbf[NN * 768];   // [x_hi,x_lo,fi_hi,fi_lo,fo_hi,fo_lo]
__device__ __align__(256) __nv_bfloat16 g_tbf[NN * 512];   // relu(h@Wf1) hi/lo
__device__ __align__(256) __nv_bfloat16 g_s1[NN * 256];    // S1 hi/lo
__device__ __align__(256) __nv_bfloat16 g_s2[NN * 256];    // S2 hi/lo

// bf16 weight tables: per logical 128-seg, 384 rows = [wh; wl; wh] (3-term split)
__device__ __align__(256) __nv_bfloat16 g_Wenc[768 * 128];
__device__ __align__(256) __nv_bfloat16 g_Wpre[384 * 512];
__device__ __align__(256) __nv_bfloat16 g_Wp2[384 * 128];
__device__ __align__(256) __nv_bfloat16 g_Wc2[384 * 128];
__device__ __align__(256) __nv_bfloat16 g_Wf1[1152 * 256];
__device__ __align__(256) __nv_bfloat16 g_Wf2[768 * 128];
__device__ __align__(256) __nv_bfloat16 g_Wcv[384 * 256];
__device__ float g_bpre[512];

__device__ int   g_indeg[NN], g_outdeg[NN];
__device__ int   g_cur1[NN], g_cur2[NN];
__device__ int   g_dst_off[NN + 1], g_src_off[NN + 1];
__device__ int   g_csr_dst[EE];
__device__ int   g_csr_src[EE];
__device__ float g_inv_dst[NN], g_inv_src[NN];
__device__ int   g_cnt[BB];

__device__ __forceinline__ __nv_bfloat16 bf_hi(float v) { return __float2bfloat16(v); }
__device__ __forceinline__ __nv_bfloat16 bf_lo(float v) {
    __nv_bfloat16 h = __float2bfloat16(v);
    return __float2bfloat16(v - __bfloat162float(h));
}

// write one logical weight element into the 3-row-block table: [wh; wl; wh]
__device__ __forceinline__ void put3(__nv_bfloat16* T, int ldn, int seg, int kk, int n, float v)
{
    __nv_bfloat16 h = bf_hi(v), l = bf_lo(v);
    size_t base = (size_t)(seg * 384 + kk) * ldn + n;
    T[base]                     = h;
    T[base + (size_t)128 * ldn] = l;
    T[base + (size_t)256 * ldn] = h;
}

// ======================= prep kernels =======================
__global__ void k_prep(const float* __restrict__ Wenc, const float* __restrict__ Wp1,
                       const float* __restrict__ Wc1, const float* __restrict__ Wp2,
                       const float* __restrict__ Wc2, const float* __restrict__ Wf1,
                       const float* __restrict__ Wf2, const float* __restrict__ Wcv,
                       const float* __restrict__ bp1, const float* __restrict__ bc1)
{
    const int T_ENC = 32768, T_PRE = 65536, T_P2 = 16384, T_C2 = 16384;
    const int T_F1 = 98304, T_F2 = 32768, T_CV = 32768;
    const int TOT = T_ENC + T_PRE + T_P2 + T_C2 + T_F1 + T_F2 + T_CV + 512;
    for (int i = blockIdx.x * blockDim.x + threadIdx.x; i < TOT;
         i += gridDim.x * blockDim.x) {
        int r = i;
        if (r < T_ENC) {                                    // enc: 2 segs x 128k x 128n
            int seg = r >> 14, kk = (r >> 7) & 127, n = r & 127;
            put3(g_Wenc, 128, seg, kk, n, Wenc[(seg * 128 + kk) * 128 + n]);
        } else if ((r -= T_ENC) < T_PRE) {                  // pre: 1 seg x 128k x 512n
            int kk = r >> 9, n = r & 511;
            int q = n >> 7, nn = n & 127;
            const float* Ws = (q < 2) ? Wp1 : Wc1;
            int krow = (q & 1) ? (128 + kk) : kk;
            put3(g_Wpre, 512, 0, kk, n, Ws[krow * 128 + nn]);
        } else if ((r -= T_PRE) < T_P2) {                   // p2: 1 seg x 128k x 128n
            int kk = r >> 7, n = r & 127;
            put3(g_Wp2, 128, 0, kk, n, Wp2[kk * 128 + n]);
        } else if ((r -= T_P2) < T_C2) {                    // c2
            int kk = r >> 7, n = r & 127;
            put3(g_Wc2, 128, 0, kk, n, Wc2[kk * 128 + n]);
        } else if ((r -= T_C2) < T_F1) {                    // f1: 3 segs x 128k x 256n
            int seg = r >> 15, kk = (r >> 8) & 127, n = r & 255;
            put3(g_Wf1, 256, seg, kk, n, Wf1[(seg * 128 + kk) * 256 + n]);
        } else if ((r -= T_F1) < T_F2) {                    // f2: 2 segs x 128k x 128n
            int seg = r >> 14, kk = (r >> 7) & 127, n = r & 127;
            put3(g_Wf2, 128, seg, kk, n, Wf2[(seg * 128 + kk) * 128 + n]);
        } else if ((r -= T_F2) < T_CV) {                    // conv: 1 seg x 128k x 256n
            int kk = r >> 8, n = r & 255;
            put3(g_Wcv, 256, 0, kk, n, Wcv[kk * 256 + n]);
        } else {                                            // combined pre bias [512]
            r -= T_CV;
            int q = r >> 7, nn = r & 127;
            g_bpre[r] = (q == 0) ? bp1[nn] : (q == 2) ? bc1[nn] : 0.f;
        }
    }
}

__global__ void k_nodes(const float* __restrict__ nodes)
{
    int i = blockIdx.x * blockDim.x + threadIdx.x;
    if (i >= NN * 64) return;
    int row = i >> 6, c4 = (i & 63) * 4;
    float4 v = *(const float4*)(nodes + (size_t)row * 256 + c4);
    int seg = c4 >> 7, kk = c4 & 127;
    __nv_bfloat16* p = g_nbf + (size_t)row * 512 + seg * 256 + kk;
    p[0] = bf_hi(v.x); p[1] = bf_hi(v.y); p[2] = bf_hi(v.z); p[3] = bf_hi(v.w);
    p[128] = bf_lo(v.x); p[129] = bf_lo(v.y); p[130] = bf_lo(v.z); p[131] = bf_lo(v.w);
}

// ======================= wmma bf16 3-term split GEMM =======================
// Logical C[M x Ntot] = Afp32[M x (nblk*128)] @ Wfp32, computed as bf16 virtual-K:
// per logical 128-seg, 3 virtual 128-blocks: A uses [hi, hi, lo] (phys [hi|lo] pairs),
// W rows are linear [wh; wl; wh]. fp32 accumulate.
#define MM_SMEM 69632

template<int EPI, bool WF32, bool WBF>
__global__ void __launch_bounds__(256) mm_bf(
    const __nv_bfloat16* __restrict__ A, int lda, int nblk,
    const __nv_bfloat16* __restrict__ W, int ldw,
    const float* __restrict__ bias,
    const int* __restrict__ mask,
    const float* __restrict__ Cprev, int ldprev,
    float* __restrict__ C, int ldc,
    __nv_bfloat16* __restrict__ BF, int ldbf, int boff,
    int M)
{
    extern __shared__ char smraw[];
    __nv_bfloat16* As = (__nv_bfloat16*)smraw;             // [128][48]
    __nv_bfloat16* Bs = (__nv_bfloat16*)(smraw + 12288);   // [32][136]
    float* Co = (float*)smraw;                             // [128][132] (reused)

    const int tid = threadIdx.x;
    const int m0 = blockIdx.x * 128, n0 = blockIdx.y * 128;
    const int warp = tid >> 5;
    const int wm = warp & 3, wn = warp >> 2;
    const int K2v = nblk * 384;

    wmma::fragment<wmma::accumulator, 16, 16, 16, float> acc[2][4];
#pragma unroll
    for (int i = 0; i < 2; i++)
#pragma unroll
        for (int j = 0; j < 4; j++) wmma::fill_fragment(acc[i][j], 0.f);

    int ar0 = m0 + (tid >> 2);        if (ar0 >= M) ar0 = M - 1;
    int ar1 = m0 + (tid >> 2) + 64;   if (ar1 >= M) ar1 = M - 1;
    const int aq = (tid & 3) * 8;
    const int br = tid >> 4;
    const int bq = (tid & 15) * 8;

    uint4 ra0, ra1, rb0, rb1;
    // virtual-block -> A physical column base: seg*256 + (t==2 ? 128 : 0)
#define LOADG(kt_) do { \
        int vb_ = (kt_) >> 7, wi_ = (kt_) & 127; \
        int seg_ = vb_ / 3, t_ = vb_ - seg_ * 3; \
        int ab_ = seg_ * 256 + ((t_ == 2) ? 128 : 0) + wi_ + aq; \
        ra0 = *(const uint4*)(A + (size_t)ar0 * lda + ab_); \
        ra1 = *(const uint4*)(A + (size_t)ar1 * lda + ab_); \
        rb0 = *(const uint4*)(W + (size_t)((kt_) + br) * ldw + n0 + bq); \
        rb1 = *(const uint4*)(W + (size_t)((kt_) + br + 16) * ldw + n0 + bq); \
    } while (0)
#define STOS() do { \
        *(uint4*)(As + (tid >> 2) * 48 + aq) = ra0; \
        *(uint4*)(As + ((tid >> 2) + 64) * 48 + aq) = ra1; \
        *(uint4*)(Bs + br * 136 + bq) = rb0; \
        *(uint4*)(Bs + (br + 16) * 136 + bq) = rb1; \
    } while (0)

    LOADG(0); STOS();
    __syncthreads();
    for (int kt = 0; kt < K2v; kt += 32) {
        bool nxt = (kt + 32) < K2v;
        if (nxt) LOADG(kt + 32);
#pragma unroll
        for (int kk = 0; kk < 32; kk += 16) {
            wmma::fragment<wmma::matrix_a, 16, 16, 16, __nv_bfloat16, wmma::row_major> af[2];
#pragma unroll
            for (int i = 0; i < 2; i++)
                wmma::load_matrix_sync(af[i], As + (wm * 32 + i * 16) * 48 + kk, 48);
#pragma unroll
            for (int j = 0; j < 4; j++) {
                wmma::fragment<wmma::matrix_b, 16, 16, 16, __nv_bfloat16, wmma::row_major> bfr;
                wmma::load_matrix_sync(bfr, Bs + kk * 136 + wn * 64 + j * 16, 136);
#pragma unroll
                for (int i = 0; i < 2; i++)
                    wmma::mma_sync(acc[i][j], af[i], bfr, acc[i][j]);
            }
        }
        __syncthreads();
        if (nxt) { STOS(); __syncthreads(); }
    }
#undef LOADG
#undef STOS

    // stage accumulators to smem (overlaps As/Bs; safe after final sync)
#pragma unroll
    for (int i = 0; i < 2; i++)
#pragma unroll
        for (int j = 0; j < 4; j++)
            wmma::store_matrix_sync(Co + (wm * 32 + i * 16) * 132 + wn * 64 + j * 16,
                                    acc[i][j], 132, wmma::mem_row_major);
    __syncthreads();

    for (int t = tid; t < 128 * 32; t += 256) {
        int row = t >> 5, c4 = (t & 31) * 4;
        int grow = m0 + row;
        if (grow >= M) continue;
        float4 v = *(float4*)(Co + row * 132 + c4);
        int gc = n0 + c4;
        float vv[4] = {v.x, v.y, v.z, v.w};
        if (EPI == 0) {
#pragma unroll
            for (int c = 0; c < 4; c++) vv[c] += bias[gc + c];
        } else if (EPI == 1) {
            if (mask[grow] > 0) {
#pragma unroll
                for (int c = 0; c < 4; c++) vv[c] += bias[gc + c];
            }
        } else if (EPI == 2) {
#pragma unroll
            for (int c = 0; c < 4; c++) vv[c] = fmaxf(vv[c] + bias[gc + c], 0.f);
        } else {
            float4 p = *(const float4*)(Cprev + (size_t)grow * ldprev + gc);
            vv[0] += bias[gc] + p.x;     vv[1] += bias[gc + 1] + p.y;
            vv[2] += bias[gc + 2] + p.z; vv[3] += bias[gc + 3] + p.w;
        }
        if (WF32) {
            float4 o; o.x = vv[0]; o.y = vv[1]; o.z = vv[2]; o.w = vv[3];
            *(float4*)(C + (size_t)grow * ldc + gc) = o;
        }
        if (WBF) {
            int hidx = boff + ((gc >> 7) * 256) + (gc & 127);
            __nv_bfloat16* p = BF + (size_t)grow * ldbf + hidx;
            *(__nv_bfloat162*)(p)       = __halves2bfloat162(bf_hi(vv[0]), bf_hi(vv[1]));
            *(__nv_bfloat162*)(p + 2)   = __halves2bfloat162(bf_hi(vv[2]), bf_hi(vv[3]));
            *(__nv_bfloat162*)(p + 128) = __halves2bfloat162(bf_lo(vv[0]), bf_lo(vv[1]));
            *(__nv_bfloat162*)(p + 130) = __halves2bfloat162(bf_lo(vv[2]), bf_lo(vv[3]));
        }
    }
}

// ======================= CSR / misc (proven R2 path) =======================
__global__ void k_zero(float* out)
{
    int i = blockIdx.x * blockDim.x + threadIdx.x;
    int stride = gridDim.x * blockDim.x;
    for (int k = i; k < NN; k += stride) {
        g_indeg[k] = 0; g_outdeg[k] = 0; g_cur1[k] = 0; g_cur2[k] = 0;
    }
    if (i < BB) g_cnt[i] = 0;
    if (i < BB * 512) out[i] = ((i & 511) < 256) ? -FLT_MAX : 0.f;
}

__global__ void k_degree(const int* __restrict__ src, const int* __restrict__ dst)
{
    int e = blockIdx.x * blockDim.x + threadIdx.x;
    if (e < EE) {
        atomicAdd(&g_indeg[dst[e]], 1);
        atomicAdd(&g_outdeg[src[e]], 1);
    }
}

__global__ void k_scan()
{
    const int* deg = (blockIdx.x == 0) ? g_indeg : g_outdeg;
    int* off       = (blockIdx.x == 0) ? g_dst_off : g_src_off;
    __shared__ int ssum[1024];
    int t = threadIdx.x;
    const int chunk = (NN + 1023) / 1024;
    int s0 = t * chunk;
    int s1 = (s0 + chunk < NN) ? s0 + chunk : NN;
    int s = 0;
    for (int i = s0; i < s1; i++) s += deg[i];
    ssum[t] = s;
    __syncthreads();
    for (int d = 1; d < 1024; d <<= 1) {
        int v = 0;
        if (t >= d) v = ssum[t - d];
        __syncthreads();
        if (t >= d) ssum[t] += v;
        __syncthreads();
    }
    int base = t ? ssum[t - 1] : 0;
    for (int i = s0; i < s1; i++) { off[i] = base; base += deg[i]; }
    if (t == 0) off[NN] = ssum[1023];
}

__global__ void k_fill(const int* __restrict__ src, const int* __restrict__ dst)
{
    int e = blockIdx.x * blockDim.x + threadIdx.x;
    if (e < EE) {
        int s = src[e], d = dst[e];
        int p = g_dst_off[d] + atomicAdd(&g_cur1[d], 1);
        g_csr_dst[p] = s;
        int q = g_src_off[s] + atomicAdd(&g_cur2[s], 1);
        g_csr_src[q] = d;
    }
}

__global__ void k_invdeg(const int* __restrict__ batch)
{
    int i = blockIdx.x * blockDim.x + threadIdx.x;
    if (i < NN) {
        int a = g_indeg[i];  g_inv_dst[i] = a ? 1.f / (float)a : 0.f;
        int b = g_outdeg[i]; g_inv_src[i] = b ? 1.f / (float)b : 0.f;
        atomicAdd(&g_cnt[batch[i]], 1);
    }
}

// edge aggregation: S[i] = inv[i]*sum_j relu(A[i]+B[j]); fp32 in (slices of g_P, ld 512),
// bf16 hi/lo out [N][256]
__global__ void k_edge_agg(const float* __restrict__ P, int aoff, int boff_,
                           const int* __restrict__ off, const int* __restrict__ csr,
                           const float* __restrict__ inv, __nv_bfloat16* __restrict__ S)
{
    int gw   = (blockIdx.x * blockDim.x + threadIdx.x) >> 5;
    int lane = threadIdx.x & 31;
    if (gw >= NN) return;
    float4 a = *(const float4*)(P + aoff + (size_t)gw * 512 + lane * 4);
    float4 acc = make_float4(0.f, 0.f, 0.f, 0.f);
    int e0 = off[gw], e1 = off[gw + 1];
    for (int e = e0; e < e1; e++) {
        int j = csr[e];
        float4 b = *(const float4*)(P + boff_ + (size_t)j * 512 + lane * 4);
        acc.x += fmaxf(a.x + b.x, 0.f);
        acc.y += fmaxf(a.y + b.y, 0.f);
        acc.z += fmaxf(a.z + b.z, 0.f);
        acc.w += fmaxf(a.w + b.w, 0.f);
    }
    float s = inv[gw];
    float r0 = acc.x * s, r1 = acc.y * s, r2 = acc.z * s, r3 = acc.w * s;
    __nv_bfloat16* p = S + (size_t)gw * 256 + lane * 4;
    *(__nv_bfloat162*)(p)       = __halves2bfloat162(bf_hi(r0), bf_hi(r1));
    *(__nv_bfloat162*)(p + 2)   = __halves2bfloat162(bf_hi(r2), bf_hi(r3));
    *(__nv_bfloat162*)(p + 128) = __halves2bfloat162(bf_lo(r0), bf_lo(r1));
    *(__nv_bfloat162*)(p + 130) = __halves2bfloat162(bf_lo(r2), bf_lo(r3));
}

// pooling
__device__ __forceinline__ void atomicMaxF(float* addr, float val)
{
    int old = __float_as_int(*addr);
    while (__int_as_float(old) < val) {
        int prev = atomicCAS((int*)addr, old, __float_as_int(val));
        if (prev == old) break;
        old = prev;
    }
}

__global__ void k_pool(const float* __restrict__ y, const int* __restrict__ batch,
                       float* __restrict__ out)
{
    int t = threadIdx.x;
    int chunk = (NN + gridDim.x - 1) / gridDim.x;
    int r0 = blockIdx.x * chunk;
    int r1 = (r0 + chunk < NN) ? r0 + chunk : NN;
    if (r0 >= r1) return;
    int g = batch[r0];
    float mx = -FLT_MAX, sm = 0.f;
    for (int r = r0; r < r1; r++) {
        int gb = batch[r];
        float v = y[(size_t)r * 256 + t];
        if (gb != g) {
            atomicMaxF(&out[g * 512 + t], mx);
            atomicAdd(&out[g * 512 + 256 + t], sm);
            g = gb; mx = -FLT_MAX; sm = 0.f;
        }
        mx = fmaxf(mx, v);
        sm += v;
    }
    atomicMaxF(&out[g * 512 + t], mx);
    atomicAdd(&out[g * 512 + 256 + t], sm);
}

__global__ void k_finalize(float* out)
{
    int b = blockIdx.x, c = threadIdx.x;
    int cnt = g_cnt[b];
    if (cnt > 0) out[b * 512 + 256 + c] *= 1.f / (float)cnt;
}

// ======================= launch =======================
extern "C" void kernel_launch(void* const* d_in, const int* in_sizes, int n_in,
                              void* d_out, int out_size)
{
    const float* nodes = (const float*)d_in[0];
    const int*   edges = (const int*)  d_in[1];
    const int*   batch = (const int*)  d_in[2];
    const float* W_enc = (const float*)d_in[3];
    const float* b_enc = (const float*)d_in[4];
    const float* Wp1   = (const float*)d_in[5];
    const float* bp1   = (const float*)d_in[6];
    const float* Wp2   = (const float*)d_in[7];
    const float* bp2   = (const float*)d_in[8];
    const float* Wc1   = (const float*)d_in[9];
    const float* bc1   = (const float*)d_in[10];
    const float* Wc2   = (const float*)d_in[11];
    const float* bc2   = (const float*)d_in[12];
    const float* Wf1   = (const float*)d_in[13];
    const float* bf1   = (const float*)d_in[14];
    const float* Wf2   = (const float*)d_in[15];
    const float* bf2   = (const float*)d_in[16];
    const float* Wconv = (const float*)d_in[17];
    const float* bconv = (const float*)d_in[18];
    float* out = (float*)d_out;

    const int* src = edges;
    const int* dst = edges + EE;

    float *x, *P, *invd, *invs, *bpre;
    __nv_bfloat16 *nbf, *cbf, *tbf, *s1, *s2;
    __nv_bfloat16 *wenc, *wpre, *wp2, *wc2, *wf1, *wf2, *wcv;
    int *indeg, *outdeg, *doff, *soff, *csrd, *csrs;
    cudaGetSymbolAddress((void**)&x, g_x);
    cudaGetSymbolAddress((void**)&P, g_P);
    cudaGetSymbolAddress((void**)&nbf, g_nbf);
    cudaGetSymbolAddress((void**)&cbf, g_cbf);
    cudaGetSymbolAddress((void**)&tbf, g_tbf);
    cudaGetSymbolAddress((void**)&s1, g_s1);
    cudaGetSymbolAddress((void**)&s2, g_s2);
    cudaGetSymbolAddress((void**)&wenc, g_Wenc);
    cudaGetSymbolAddress((void**)&wpre, g_Wpre);
    cudaGetSymbolAddress((void**)&wp2, g_Wp2);
    cudaGetSymbolAddress((void**)&wc2, g_Wc2);
    cudaGetSymbolAddress((void**)&wf1, g_Wf1);
    cudaGetSymbolAddress((void**)&wf2, g_Wf2);
    cudaGetSymbolAddress((void**)&wcv, g_Wcv);
    cudaGetSymbolAddress((void**)&bpre, g_bpre);
    cudaGetSymbolAddress((void**)&invd, g_inv_dst);
    cudaGetSymbolAddress((void**)&invs, g_inv_src);
    cudaGetSymbolAddress((void**)&indeg, g_indeg);
    cudaGetSymbolAddress((void**)&outdeg, g_outdeg);
    cudaGetSymbolAddress((void**)&doff, g_dst_off);
    cudaGetSymbolAddress((void**)&soff, g_src_off);
    cudaGetSymbolAddress((void**)&csrd, g_csr_dst);
    cudaGetSymbolAddress((void**)&csrs, g_csr_src);

    cudaFuncSetAttribute(mm_bf<0, true, true>,  cudaFuncAttributeMaxDynamicSharedMemorySize, MM_SMEM);
    cudaFuncSetAttribute(mm_bf<0, true, false>, cudaFuncAttributeMaxDynamicSharedMemorySize, MM_SMEM);
    cudaFuncSetAttribute(mm_bf<1, false, true>, cudaFuncAttributeMaxDynamicSharedMemorySize, MM_SMEM);
    cudaFuncSetAttribute(mm_bf<2, false, true>, cudaFuncAttributeMaxDynamicSharedMemorySize, MM_SMEM);
    cudaFuncSetAttribute(mm_bf<3, true, true>,  cudaFuncAttributeMaxDynamicSharedMemorySize, MM_SMEM);

    const int gx = (NN + 127) / 128;   // 391
    dim3 blk(256);
    dim3 g1(gx, 1), g2(gx, 2), g4(gx, 4);
    int egrid = (EE + 255) / 256;

    // CSR + degrees + init + bf16 prep
    k_zero<<<256, 256>>>(out);
    k_degree<<<egrid, 256>>>(src, dst);
    k_scan<<<2, 1024>>>();
    k_fill<<<egrid, 256>>>(src, dst);
    k_invdeg<<<(NN + 255) / 256, 256>>>(batch);
    k_prep<<<1024, 256>>>(W_enc, Wp1, Wc1, Wp2, Wc2, Wf1, Wf2, Wconv, bp1, bc1);
    k_nodes<<<(NN * 64 + 255) / 256, 256>>>(nodes);

    // encoder: x = nodes @ W_enc + b_enc ; fp32 x and bf16 cbf x-slot
    mm_bf<0, true, true><<<g1, blk, MM_SMEM>>>(nbf, 512, 2, wenc, 128,
        b_enc, nullptr, nullptr, 0, x, 128, cbf, 768, 0, NN);

    for (int it = 0; it < 2; it++) {
        // fused pre-edge GEMM: P = x @ [Wp1_i|Wp1_j|Wc1_i|Wc1_j] + [bp1|0|bc1|0]
        mm_bf<0, true, false><<<g4, blk, MM_SMEM>>>(cbf, 768, 1, wpre, 512,
            bpre, nullptr, nullptr, 0, P, 512, nullptr, 0, 0, NN);
        // edge sweeps (linearity of W2 => sum relu first, GEMM after)
        k_edge_agg<<<6250, 256>>>(P, 0,   128, doff, csrd, invd, s1);  // parent (by dst)
        k_edge_agg<<<6250, 256>>>(P, 256, 384, soff, csrs, invs, s2);  // child (by src)
        // second MLP layer on normalized sums -> bf16 into cbf fi/fo slots
        mm_bf<1, false, true><<<g1, blk, MM_SMEM>>>(s1, 256, 1, wp2, 128,
            bp2, indeg, nullptr, 0, nullptr, 0, cbf, 768, 256, NN);
        mm_bf<1, false, true><<<g1, blk, MM_SMEM>>>(s2, 256, 1, wc2, 128,
            bc2, outdeg, nullptr, 0, nullptr, 0, cbf, 768, 512, NN);
        // t = relu([x|fi|fo] @ Wf1 + bf1) -> bf16 tbf
        mm_bf<2, false, true><<<g2, blk, MM_SMEM>>>(cbf, 768, 3, wf1, 256,
            bf1, nullptr, nullptr, 0, nullptr, 0, tbf, 512, 0, NN);
        // x = x + t @ Wf2 + bf2 -> fp32 x and bf16 cbf x-slot
        mm_bf<3, true, true><<<g1, blk, MM_SMEM>>>(tbf, 512, 2, wf2, 128,
            bf2, nullptr, x, 128, x, 128, cbf, 768, 0, NN);
    }

    // conv1d(k=1): y = x @ Wconv + bconv -> fp32 into P (ld 256)
    mm_bf<0, true, false><<<g2, blk, MM_SMEM>>>(cbf, 768, 1, wcv, 256,
        bconv, nullptr, nullptr, 0, P, 256, nullptr, 0, 0, NN);

    // global max / mean pool per graph
    k_pool<<<128, 256>>>(P, batch, out);
    k_finalize<<<BB, 256>>>(out);
}

// round 11
// speedup vs baseline: 1.5121x; 1.0821x over previous
#include <cuda_runtime.h>
#include <cuda_bf16.h>
#include <mma.h>
#include <cfloat>
#include <cstdint>
using namespace nvcuda;

#define NN 50000
#define EE 800000
#define BB 8

// ======================= device global scratch =======================
__device__ float g_x[NN * 128];          // node embedding fp32
__device__ float g_P[NN * 512];          // [A1|B1|A2|B2] fp32; reused as y[N,256]
__device__ __align__(256) __nv_bfloat16 g_nbf[NN * 512];   // nodes hi/lo (per-128 seg pairs)
__device__ __align__(256) __nv_bfloat16 g_cbf[NN * 768];   // [x_hi,x_lo,fi_hi,fi_lo,fo_hi,fo_lo]
__device__ __align__(256) __nv_bfloat16 g_tbf[NN * 512];   // relu(h@Wf1) hi/lo
__device__ __align__(256) __nv_bfloat16 g_s1[NN * 256];    // S1 hi/lo
__device__ __align__(256) __nv_bfloat16 g_s2[NN * 256];    // S2 hi/lo

// bf16 weight tables: per logical 128-seg, 384 rows = [wh; wl; wh] (3-term split)
__device__ __align__(256) __nv_bfloat16 g_Wenc[768 * 128];
__device__ __align__(256) __nv_bfloat16 g_Wpre[384 * 512];
__device__ __align__(256) __nv_bfloat16 g_Wp2[384 * 128];
__device__ __align__(256) __nv_bfloat16 g_Wc2[384 * 128];
__device__ __align__(256) __nv_bfloat16 g_Wf1[1152 * 256];
__device__ __align__(256) __nv_bfloat16 g_Wf2[768 * 128];
__device__ __align__(256) __nv_bfloat16 g_Wcv[384 * 256];
__device__ float g_bpre[512];

__device__ int   g_indeg[NN], g_outdeg[NN];
__device__ int   g_cur1[NN], g_cur2[NN];
__device__ int   g_dst_off[NN + 1], g_src_off[NN + 1];
__device__ int   g_csr_dst[EE];
__device__ int   g_csr_src[EE];
__device__ float g_inv_dst[NN], g_inv_src[NN];
__device__ int   g_cnt[BB];

__device__ __forceinline__ __nv_bfloat16 bf_hi(float v) { return __float2bfloat16(v); }
__device__ __forceinline__ __nv_bfloat16 bf_lo(float v) {
    __nv_bfloat16 h = __float2bfloat16(v);
    return __float2bfloat16(v - __bfloat162float(h));
}

// write one logical weight element into the 3-row-block table: [wh; wl; wh]
__device__ __forceinline__ void put3(__nv_bfloat16* T, int ldn, int seg, int kk, int n, float v)
{
    __nv_bfloat16 h = bf_hi(v), l = bf_lo(v);
    size_t base = (size_t)(seg * 384 + kk) * ldn + n;
    T[base]                     = h;
    T[base + (size_t)128 * ldn] = l;
    T[base + (size_t)256 * ldn] = h;
}

// ======================= prep kernels =======================
__global__ void k_prep(const float* __restrict__ Wenc, const float* __restrict__ Wp1,
                       const float* __restrict__ Wc1, const float* __restrict__ Wp2,
                       const float* __restrict__ Wc2, const float* __restrict__ Wf1,
                       const float* __restrict__ Wf2, const float* __restrict__ Wcv,
                       const float* __restrict__ bp1, const float* __restrict__ bc1)
{
    const int T_ENC = 32768, T_PRE = 65536, T_P2 = 16384, T_C2 = 16384;
    const int T_F1 = 98304, T_F2 = 32768, T_CV = 32768;
    const int TOT = T_ENC + T_PRE + T_P2 + T_C2 + T_F1 + T_F2 + T_CV + 512;
    for (int i = blockIdx.x * blockDim.x + threadIdx.x; i < TOT;
         i += gridDim.x * blockDim.x) {
        int r = i;
        if (r < T_ENC) {                                    // enc: 2 segs x 128k x 128n
            int seg = r >> 14, kk = (r >> 7) & 127, n = r & 127;
            put3(g_Wenc, 128, seg, kk, n, Wenc[(seg * 128 + kk) * 128 + n]);
        } else if ((r -= T_ENC) < T_PRE) {                  // pre: 1 seg x 128k x 512n
            int kk = r >> 9, n = r & 511;
            int q = n >> 7, nn = n & 127;
            const float* Ws = (q < 2) ? Wp1 : Wc1;
            int krow = (q & 1) ? (128 + kk) : kk;
            put3(g_Wpre, 512, 0, kk, n, Ws[krow * 128 + nn]);
        } else if ((r -= T_PRE) < T_P2) {                   // p2: 1 seg x 128k x 128n
            int kk = r >> 7, n = r & 127;
            put3(g_Wp2, 128, 0, kk, n, Wp2[kk * 128 + n]);
        } else if ((r -= T_P2) < T_C2) {                    // c2
            int kk = r >> 7, n = r & 127;
            put3(g_Wc2, 128, 0, kk, n, Wc2[kk * 128 + n]);
        } else if ((r -= T_C2) < T_F1) {                    // f1: 3 segs x 128k x 256n
            int seg = r >> 15, kk = (r >> 8) & 127, n = r & 255;
            put3(g_Wf1, 256, seg, kk, n, Wf1[(seg * 128 + kk) * 256 + n]);
        } else if ((r -= T_F1) < T_F2) {                    // f2: 2 segs x 128k x 128n
            int seg = r >> 14, kk = (r >> 7) & 127, n = r & 127;
            put3(g_Wf2, 128, seg, kk, n, Wf2[(seg * 128 + kk) * 128 + n]);
        } else if ((r -= T_F2) < T_CV) {                    // conv: 1 seg x 128k x 256n
            int kk = r >> 8, n = r & 255;
            put3(g_Wcv, 256, 0, kk, n, Wcv[kk * 256 + n]);
        } else {                                            // combined pre bias [512]
            r -= T_CV;
            int q = r >> 7, nn = r & 127;
            g_bpre[r] = (q == 0) ? bp1[nn] : (q == 2) ? bc1[nn] : 0.f;
        }
    }
}

__global__ void k_nodes(const float* __restrict__ nodes)
{
    int i = blockIdx.x * blockDim.x + threadIdx.x;
    if (i >= NN * 64) return;
    int row = i >> 6, c4 = (i & 63) * 4;
    float4 v = *(const float4*)(nodes + (size_t)row * 256 + c4);
    int seg = c4 >> 7, kk = c4 & 127;
    __nv_bfloat16* p = g_nbf + (size_t)row * 512 + seg * 256 + kk;
    p[0] = bf_hi(v.x); p[1] = bf_hi(v.y); p[2] = bf_hi(v.z); p[3] = bf_hi(v.w);
    p[128] = bf_lo(v.x); p[129] = bf_lo(v.y); p[130] = bf_lo(v.z); p[131] = bf_lo(v.w);
}

// ======================= wmma bf16 3-term split GEMM (cp.async 4-stage) ==============
// Logical C[M x Ntot] = Afp32[M x (nblk*128)] @ Wfp32, computed in bf16 virtual-K:
// per logical 128-seg, 3 virtual 128-blocks: A uses [hi, hi, lo], W rows [wh; wl; wh].
#define NST 4
#define STAGE_B 20992            // As 128x48x2 (12288) + Bs 32x136x2 (8704)
#define MM_SMEM 83968            // 4 stages; epilogue Co 128x132x4 = 67584 overlays

__device__ __forceinline__ uint32_t s2u(const void* p){
    uint32_t a;
    asm("{ .reg .u64 t; cvta.to.shared.u64 t, %1; cvt.u32.u64 %0, t; }" : "=r"(a) : "l"(p));
    return a;
}
__device__ __forceinline__ void cpa16(uint32_t s, const void* g){
    asm volatile("cp.async.cg.shared.global [%0], [%1], 16;" :: "r"(s), "l"(g));
}
#define CP_COMMIT() asm volatile("cp.async.commit_group;" ::: "memory")
#define CP_WAIT(n)  asm volatile("cp.async.wait_group %0;" :: "n"(n) : "memory")

template<int EPI, bool WF32, bool WBF>
__global__ void __launch_bounds__(256, 2) mm_bf(
    const __nv_bfloat16* __restrict__ A, int lda, int nblk,
    const __nv_bfloat16* __restrict__ W, int ldw,
    const float* __restrict__ bias,
    const int* __restrict__ mask,
    const float* __restrict__ Cprev, int ldprev,
    float* __restrict__ C, int ldc,
    __nv_bfloat16* __restrict__ BF, int ldbf, int boff,
    int M)
{
    extern __shared__ char smraw[];
    float* Co = (float*)smraw;                             // [128][132] (epilogue reuse)

    const int tid = threadIdx.x;
    const int m0 = blockIdx.x * 128, n0 = blockIdx.y * 128;
    const int warp = tid >> 5;
    const int wm = warp & 3, wn = warp >> 2;
    const int nt = nblk * 12;                              // 32-wide K tiles (virtual)

    wmma::fragment<wmma::accumulator, 16, 16, 16, float> acc[2][4];
#pragma unroll
    for (int i = 0; i < 2; i++)
#pragma unroll
        for (int j = 0; j < 4; j++) wmma::fill_fragment(acc[i][j], 0.f);

    int ar0 = m0 + (tid >> 2);        if (ar0 >= M) ar0 = M - 1;
    int ar1 = ar0 + 64;               if (ar1 >= M) ar1 = M - 1;
    const int aq = (tid & 3) * 8;     // A k-offset within 32-tile (per-thread 16B)
    const int br = tid >> 4;          // B row 0..15 (+16)
    const int bq = (tid & 15) * 8;

    const uint32_t smb = s2u(smraw);

    // issue one stage's loads (A 128x32 tile + W 32x128 tile) with cp.async
#define ISSUE(kt_, st_) do { \
        uint32_t sA_ = smb + (st_) * STAGE_B; \
        uint32_t sB_ = sA_ + 12288; \
        int vb_ = (kt_) >> 7, wi_ = (kt_) & 127; \
        int seg_ = vb_ / 3, t_ = vb_ - seg_ * 3; \
        int ab_ = seg_ * 256 + ((t_ == 2) ? 128 : 0) + wi_ + aq; \
        cpa16(sA_ + (uint32_t)(((tid >> 2) * 48 + aq) * 2), A + (size_t)ar0 * lda + ab_); \
        cpa16(sA_ + (uint32_t)((((tid >> 2) + 64) * 48 + aq) * 2), A + (size_t)ar1 * lda + ab_); \
        cpa16(sB_ + (uint32_t)((br * 136 + bq) * 2), W + (size_t)((kt_) + br) * ldw + n0 + bq); \
        cpa16(sB_ + (uint32_t)(((br + 16) * 136 + bq) * 2), W + (size_t)((kt_) + br + 16) * ldw + n0 + bq); \
    } while (0)

#pragma unroll
    for (int i = 0; i < NST - 1; i++) {        // nt >= 12 always
        ISSUE(i * 32, i);
        CP_COMMIT();
    }

    for (int i = 0; i < nt; i++) {
        CP_WAIT(NST - 2);
        __syncthreads();
        int nx = i + NST - 1;
        if (nx < nt) ISSUE(nx * 32, nx & (NST - 1));
        CP_COMMIT();

        const __nv_bfloat16* As = (const __nv_bfloat16*)(smraw + (i & (NST - 1)) * STAGE_B);
        const __nv_bfloat16* Bs = As + 12288 / 2;
#pragma unroll
        for (int kk = 0; kk < 32; kk += 16) {
            wmma::fragment<wmma::matrix_a, 16, 16, 16, __nv_bfloat16, wmma::row_major> af[2];
#pragma unroll
            for (int a2 = 0; a2 < 2; a2++)
                wmma::load_matrix_sync(af[a2], As + (wm * 32 + a2 * 16) * 48 + kk, 48);
#pragma unroll
            for (int j = 0; j < 4; j++) {
                wmma::fragment<wmma::matrix_b, 16, 16, 16, __nv_bfloat16, wmma::row_major> bfr;
                wmma::load_matrix_sync(bfr, Bs + kk * 136 + wn * 64 + j * 16, 136);
#pragma unroll
                for (int a2 = 0; a2 < 2; a2++)
                    wmma::mma_sync(acc[a2][j], af[a2], bfr, acc[a2][j]);
            }
        }
    }
#undef ISSUE
    __syncthreads();

    // stage accumulators to smem (overlays pipeline buffers)
#pragma unroll
    for (int i = 0; i < 2; i++)
#pragma unroll
        for (int j = 0; j < 4; j++)
            wmma::store_matrix_sync(Co + (wm * 32 + i * 16) * 132 + wn * 64 + j * 16,
                                    acc[i][j], 132, wmma::mem_row_major);
    __syncthreads();

    for (int t = tid; t < 128 * 32; t += 256) {
        int row = t >> 5, c4 = (t & 31) * 4;
        int grow = m0 + row;
        if (grow >= M) continue;
        float4 v = *(float4*)(Co + row * 132 + c4);
        int gc = n0 + c4;
        float vv[4] = {v.x, v.y, v.z, v.w};
        if (EPI == 0) {
#pragma unroll
            for (int c = 0; c < 4; c++) vv[c] += bias[gc + c];
        } else if (EPI == 1) {
            if (mask[grow] > 0) {
#pragma unroll
                for (int c = 0; c < 4; c++) vv[c] += bias[gc + c];
            }
        } else if (EPI == 2) {
#pragma unroll
            for (int c = 0; c < 4; c++) vv[c] = fmaxf(vv[c] + bias[gc + c], 0.f);
        } else {
            float4 p = *(const float4*)(Cprev + (size_t)grow * ldprev + gc);
            vv[0] += bias[gc] + p.x;     vv[1] += bias[gc + 1] + p.y;
            vv[2] += bias[gc + 2] + p.z; vv[3] += bias[gc + 3] + p.w;
        }
        if (WF32) {
            float4 o; o.x = vv[0]; o.y = vv[1]; o.z = vv[2]; o.w = vv[3];
            *(float4*)(C + (size_t)grow * ldc + gc) = o;
        }
        if (WBF) {
            int hidx = boff + ((gc >> 7) * 256) + (gc & 127);
            __nv_bfloat16* p = BF + (size_t)grow * ldbf + hidx;
            *(__nv_bfloat162*)(p)       = __halves2bfloat162(bf_hi(vv[0]), bf_hi(vv[1]));
            *(__nv_bfloat162*)(p + 2)   = __halves2bfloat162(bf_hi(vv[2]), bf_hi(vv[3]));
            *(__nv_bfloat162*)(p + 128) = __halves2bfloat162(bf_lo(vv[0]), bf_lo(vv[1]));
            *(__nv_bfloat162*)(p + 130) = __halves2bfloat162(bf_lo(vv[2]), bf_lo(vv[3]));
        }
    }
}

// ======================= CSR / misc (proven R2 path) =======================
__global__ void k_zero(float* out)
{
    int i = blockIdx.x * blockDim.x + threadIdx.x;
    int stride = gridDim.x * blockDim.x;
    for (int k = i; k < NN; k += stride) {
        g_indeg[k] = 0; g_outdeg[k] = 0; g_cur1[k] = 0; g_cur2[k] = 0;
    }
    if (i < BB) g_cnt[i] = 0;
    if (i < BB * 512) out[i] = ((i & 511) < 256) ? -FLT_MAX : 0.f;
}

__global__ void k_degree(const int* __restrict__ src, const int* __restrict__ dst)
{
    int e = blockIdx.x * blockDim.x + threadIdx.x;
    if (e < EE) {
        atomicAdd(&g_indeg[dst[e]], 1);
        atomicAdd(&g_outdeg[src[e]], 1);
    }
}

__global__ void k_scan()
{
    const int* deg = (blockIdx.x == 0) ? g_indeg : g_outdeg;
    int* off       = (blockIdx.x == 0) ? g_dst_off : g_src_off;
    __shared__ int ssum[1024];
    int t = threadIdx.x;
    const int chunk = (NN + 1023) / 1024;
    int s0 = t * chunk;
    int s1 = (s0 + chunk < NN) ? s0 + chunk : NN;
    int s = 0;
    for (int i = s0; i < s1; i++) s += deg[i];
    ssum[t] = s;
    __syncthreads();
    for (int d = 1; d < 1024; d <<= 1) {
        int v = 0;
        if (t >= d) v = ssum[t - d];
        __syncthreads();
        if (t >= d) ssum[t] += v;
        __syncthreads();
    }
    int base = t ? ssum[t - 1] : 0;
    for (int i = s0; i < s1; i++) { off[i] = base; base += deg[i]; }
    if (t == 0) off[NN] = ssum[1023];
}

__global__ void k_fill(const int* __restrict__ src, const int* __restrict__ dst)
{
    int e = blockIdx.x * blockDim.x + threadIdx.x;
    if (e < EE) {
        int s = src[e], d = dst[e];
        int p = g_dst_off[d] + atomicAdd(&g_cur1[d], 1);
        g_csr_dst[p] = s;
        int q = g_src_off[s] + atomicAdd(&g_cur2[s], 1);
        g_csr_src[q] = d;
    }
}

__global__ void k_invdeg(const int* __restrict__ batch)
{
    int i = blockIdx.x * blockDim.x + threadIdx.x;
    if (i < NN) {
        int a = g_indeg[i];  g_inv_dst[i] = a ? 1.f / (float)a : 0.f;
        int b = g_outdeg[i]; g_inv_src[i] = b ? 1.f / (float)b : 0.f;
        atomicAdd(&g_cnt[batch[i]], 1);
    }
}

// edge aggregation: S[i] = inv[i]*sum_j relu(A[i]+B[j]); fp32 in (slices of g_P, ld 512),
// bf16 hi/lo out [N][256]
__global__ void k_edge_agg(const float* __restrict__ P, int aoff, int boff_,
                           const int* __restrict__ off, const int* __restrict__ csr,
                           const float* __restrict__ inv, __nv_bfloat16* __restrict__ S)
{
    int gw   = (blockIdx.x * blockDim.x + threadIdx.x) >> 5;
    int lane = threadIdx.x & 31;
    if (gw >= NN) return;
    float4 a = *(const float4*)(P + aoff + (size_t)gw * 512 + lane * 4);
    float4 acc = make_float4(0.f, 0.f, 0.f, 0.f);
    int e0 = off[gw], e1 = off[gw + 1];
    for (int e = e0; e < e1; e++) {
        int j = csr[e];
        float4 b = *(const float4*)(P + boff_ + (size_t)j * 512 + lane * 4);
        acc.x += fmaxf(a.x + b.x, 0.f);
        acc.y += fmaxf(a.y + b.y, 0.f);
        acc.z += fmaxf(a.z + b.z, 0.f);
        acc.w += fmaxf(a.w + b.w, 0.f);
    }
    float s = inv[gw];
    float r0 = acc.x * s, r1 = acc.y * s, r2 = acc.z * s, r3 = acc.w * s;
    __nv_bfloat16* p = S + (size_t)gw * 256 + lane * 4;
    *(__nv_bfloat162*)(p)       = __halves2bfloat162(bf_hi(r0), bf_hi(r1));
    *(__nv_bfloat162*)(p + 2)   = __halves2bfloat162(bf_hi(r2), bf_hi(r3));
    *(__nv_bfloat162*)(p + 128) = __halves2bfloat162(bf_lo(r0), bf_lo(r1));
    *(__nv_bfloat162*)(p + 130) = __halves2bfloat162(bf_lo(r2), bf_lo(r3));
}

// pooling
__device__ __forceinline__ void atomicMaxF(float* addr, float val)
{
    int old = __float_as_int(*addr);
    while (__int_as_float(old) < val) {
        int prev = atomicCAS((int*)addr, old, __float_as_int(val));
        if (prev == old) break;
        old = prev;
    }
}

__global__ void k_pool(const float* __restrict__ y, const int* __restrict__ batch,
                       float* __restrict__ out)
{
    int t = threadIdx.x;
    int chunk = (NN + gridDim.x - 1) / gridDim.x;
    int r0 = blockIdx.x * chunk;
    int r1 = (r0 + chunk < NN) ? r0 + chunk : NN;
    if (r0 >= r1) return;
    int g = batch[r0];
    float mx = -FLT_MAX, sm = 0.f;
    for (int r = r0; r < r1; r++) {
        int gb = batch[r];
        float v = y[(size_t)r * 256 + t];
        if (gb != g) {
            atomicMaxF(&out[g * 512 + t], mx);
            atomicAdd(&out[g * 512 + 256 + t], sm);
            g = gb; mx = -FLT_MAX; sm = 0.f;
        }
        mx = fmaxf(mx, v);
        sm += v;
    }
    atomicMaxF(&out[g * 512 + t], mx);
    atomicAdd(&out[g * 512 + 256 + t], sm);
}

__global__ void k_finalize(float* out)
{
    int b = blockIdx.x, c = threadIdx.x;
    int cnt = g_cnt[b];
    if (cnt > 0) out[b * 512 + 256 + c] *= 1.f / (float)cnt;
}

// ======================= launch =======================
extern "C" void kernel_launch(void* const* d_in, const int* in_sizes, int n_in,
                              void* d_out, int out_size)
{
    const float* nodes = (const float*)d_in[0];
    const int*   edges = (const int*)  d_in[1];
    const int*   batch = (const int*)  d_in[2];
    const float* W_enc = (const float*)d_in[3];
    const float* b_enc = (const float*)d_in[4];
    const float* Wp1   = (const float*)d_in[5];
    const float* bp1   = (const float*)d_in[6];
    const float* Wp2   = (const float*)d_in[7];
    const float* bp2   = (const float*)d_in[8];
    const float* Wc1   = (const float*)d_in[9];
    const float* bc1   = (const float*)d_in[10];
    const float* Wc2   = (const float*)d_in[11];
    const float* bc2   = (const float*)d_in[12];
    const float* Wf1   = (const float*)d_in[13];
    const float* bf1   = (const float*)d_in[14];
    const float* Wf2   = (const float*)d_in[15];
    const float* bf2   = (const float*)d_in[16];
    const float* Wconv = (const float*)d_in[17];
    const float* bconv = (const float*)d_in[18];
    float* out = (float*)d_out;

    const int* src = edges;
    const int* dst = edges + EE;

    float *x, *P, *invd, *invs, *bpre;
    __nv_bfloat16 *nbf, *cbf, *tbf, *s1, *s2;
    __nv_bfloat16 *wenc, *wpre, *wp2, *wc2, *wf1, *wf2, *wcv;
    int *indeg, *outdeg, *doff, *soff, *csrd, *csrs;
    cudaGetSymbolAddress((void**)&x, g_x);
    cudaGetSymbolAddress((void**)&P, g_P);
    cudaGetSymbolAddress((void**)&nbf, g_nbf);
    cudaGetSymbolAddress((void**)&cbf, g_cbf);
    cudaGetSymbolAddress((void**)&tbf, g_tbf);
    cudaGetSymbolAddress((void**)&s1, g_s1);
    cudaGetSymbolAddress((void**)&s2, g_s2);
    cudaGetSymbolAddress((void**)&wenc, g_Wenc);
    cudaGetSymbolAddress((void**)&wpre, g_Wpre);
    cudaGetSymbolAddress((void**)&wp2, g_Wp2);
    cudaGetSymbolAddress((void**)&wc2, g_Wc2);
    cudaGetSymbolAddress((void**)&wf1, g_Wf1);
    cudaGetSymbolAddress((void**)&wf2, g_Wf2);
    cudaGetSymbolAddress((void**)&wcv, g_Wcv);
    cudaGetSymbolAddress((void**)&bpre, g_bpre);
    cudaGetSymbolAddress((void**)&invd, g_inv_dst);
    cudaGetSymbolAddress((void**)&invs, g_inv_src);
    cudaGetSymbolAddress((void**)&indeg, g_indeg);
    cudaGetSymbolAddress((void**)&outdeg, g_outdeg);
    cudaGetSymbolAddress((void**)&doff, g_dst_off);
    cudaGetSymbolAddress((void**)&soff, g_src_off);
    cudaGetSymbolAddress((void**)&csrd, g_csr_dst);
    cudaGetSymbolAddress((void**)&csrs, g_csr_src);

    cudaFuncSetAttribute(mm_bf<0, true, true>,  cudaFuncAttributeMaxDynamicSharedMemorySize, MM_SMEM);
    cudaFuncSetAttribute(mm_bf<0, true, false>, cudaFuncAttributeMaxDynamicSharedMemorySize, MM_SMEM);
    cudaFuncSetAttribute(mm_bf<1, false, true>, cudaFuncAttributeMaxDynamicSharedMemorySize, MM_SMEM);
    cudaFuncSetAttribute(mm_bf<2, false, true>, cudaFuncAttributeMaxDynamicSharedMemorySize, MM_SMEM);
    cudaFuncSetAttribute(mm_bf<3, true, true>,  cudaFuncAttributeMaxDynamicSharedMemorySize, MM_SMEM);

    const int gx = (NN + 127) / 128;   // 391
    dim3 blk(256);
    dim3 g1(gx, 1), g2(gx, 2), g4(gx, 4);
    int egrid = (EE + 255) / 256;

    // CSR + degrees + init + bf16 prep
    k_zero<<<256, 256>>>(out);
    k_degree<<<egrid, 256>>>(src, dst);
    k_scan<<<2, 1024>>>();
    k_fill<<<egrid, 256>>>(src, dst);
    k_invdeg<<<(NN + 255) / 256, 256>>>(batch);
    k_prep<<<1024, 256>>>(W_enc, Wp1, Wc1, Wp2, Wc2, Wf1, Wf2, Wconv, bp1, bc1);
    k_nodes<<<(NN * 64 + 255) / 256, 256>>>(nodes);

    // encoder: x = nodes @ W_enc + b_enc ; fp32 x and bf16 cbf x-slot
    mm_bf<0, true, true><<<g1, blk, MM_SMEM>>>(nbf, 512, 2, wenc, 128,
        b_enc, nullptr, nullptr, 0, x, 128, cbf, 768, 0, NN);

    for (int it = 0; it < 2; it++) {
        // fused pre-edge GEMM: P = x @ [Wp1_i|Wp1_j|Wc1_i|Wc1_j] + [bp1|0|bc1|0]
        mm_bf<0, true, false><<<g4, blk, MM_SMEM>>>(cbf, 768, 1, wpre, 512,
            bpre, nullptr, nullptr, 0, P, 512, nullptr, 0, 0, NN);
        // edge sweeps (linearity of W2 => sum relu first, GEMM after)
        k_edge_agg<<<6250, 256>>>(P, 0,   128, doff, csrd, invd, s1);  // parent (by dst)
        k_edge_agg<<<6250, 256>>>(P, 256, 384, soff, csrs, invs, s2);  // child (by src)
        // second MLP layer on normalized sums -> bf16 into cbf fi/fo slots
        mm_bf<1, false, true><<<g1, blk, MM_SMEM>>>(s1, 256, 1, wp2, 128,
            bp2, indeg, nullptr, 0, nullptr, 0, cbf, 768, 256, NN);
        mm_bf<1, false, true><<<g1, blk, MM_SMEM>>>(s2, 256, 1, wc2, 128,
            bc2, outdeg, nullptr, 0, nullptr, 0, cbf, 768, 512, NN);
        // t = relu([x|fi|fo] @ Wf1 + bf1) -> bf16 tbf
        mm_bf<2, false, true><<<g2, blk, MM_SMEM>>>(cbf, 768, 3, wf1, 256,
            bf1, nullptr, nullptr, 0, nullptr, 0, tbf, 512, 0, NN);
        // x = x + t @ Wf2 + bf2 -> fp32 x and bf16 cbf x-slot
        mm_bf<3, true, true><<<g1, blk, MM_SMEM>>>(tbf, 512, 2, wf2, 128,
            bf2, nullptr, x, 128, x, 128, cbf, 768, 0, NN);
    }

    // conv1d(k=1): y = x @ Wconv + bconv -> fp32 into P (ld 256)
    mm_bf<0, true, false><<<g2, blk, MM_SMEM>>>(cbf, 768, 1, wcv, 256,
        bconv, nullptr, nullptr, 0, P, 256, nullptr, 0, 0, NN);

    // global max / mean pool per graph
    k_pool<<<128, 256>>>(P, batch, out);
    k_finalize<<<BB, 256>>>(out);
}